// round 4
// baseline (speedup 1.0000x reference)
#include <cuda_runtime.h>
#include <cuda_bf16.h>
#include <math.h>

#define VOCAB 50000
#define EMBED 512
#define COMP  300
#define BATCH 2048
#define SEQL  200

// Scratch (no allocations allowed -> __device__ globals)
__device__ float g_Wt[(size_t)VOCAB * EMBED];     // W_hidden transposed: [VOCAB, EMBED]
__device__ float g_Wpit[(size_t)EMBED * COMP];    // W_pi transposed:     [EMBED, COMP]
__device__ float g_hidden[(size_t)BATCH * EMBED]; // tanh hidden:         [BATCH, EMBED]
__device__ int   g_is64;                          // 1 if words buffer is int64

// ---------------------------------------------------------------------------
// Detect whether the words buffer is int64 (little-endian: odd int32 words all
// zero) or int32. Deterministic for fixed input.
// ---------------------------------------------------------------------------
__global__ void detect_dtype_k(const int* __restrict__ w32) {
    if (threadIdx.x == 0) {
        int all_zero_odd = 1;
        for (int i = 1; i < 128; i += 2)
            if (w32[i] != 0) { all_zero_odd = 0; break; }
        g_is64 = all_zero_odd;
    }
}

// ---------------------------------------------------------------------------
// Generic tiled transpose: in[rows, cols] -> out[cols, rows]
// ---------------------------------------------------------------------------
__global__ void transpose_k(const float* __restrict__ in, float* __restrict__ out,
                            int rows, int cols) {
    __shared__ float tile[32][33];
    int c0 = blockIdx.x * 32, r0 = blockIdx.y * 32;
    int x = c0 + threadIdx.x;
#pragma unroll
    for (int i = 0; i < 32; i += 8) {
        int y = r0 + threadIdx.y + i;
        if (x < cols && y < rows)
            tile[threadIdx.y + i][threadIdx.x] = in[(size_t)y * cols + x];
    }
    __syncthreads();
    x = r0 + threadIdx.x;
#pragma unroll
    for (int i = 0; i < 32; i += 8) {
        int y = c0 + threadIdx.y + i;
        if (x < rows && y < cols)
            out[(size_t)y * rows + x] = tile[threadIdx.x][threadIdx.y + i];
    }
}

// ---------------------------------------------------------------------------
// Bag-of-words gather-sum + tanh.  One block per batch row, 512 threads
// (one per embedding dim).  Dedup words (duplicates collapse to 1.0).
// ---------------------------------------------------------------------------
__global__ __launch_bounds__(EMBED) void bow_kernel(
    const void* __restrict__ words,
    const float* __restrict__ b_hidden,
    float* __restrict__ hidden) {
    __shared__ int sw[SEQL];
    __shared__ int flag[SEQL];
    __shared__ int list[SEQL];
    __shared__ int nkeep;

    int b = blockIdx.x;
    int tid = threadIdx.x;
    int is64 = g_is64;

    if (tid < SEQL) {
        int w;
        if (is64)
            w = (int)((const long long*)words)[(size_t)b * SEQL + tid];
        else
            w = ((const int*)words)[(size_t)b * SEQL + tid];
        // clamp (guard against any remaining dtype surprise: fail soft, not fault)
        if (w < 0) w = 0;
        if (w >= VOCAB) w = VOCAB - 1;
        sw[tid] = w;
    }
    __syncthreads();
    if (tid < SEQL) {
        int w = sw[tid], f = 1;
        for (int i = 0; i < tid; i++)
            if (sw[i] == w) { f = 0; break; }
        flag[tid] = f;
    }
    __syncthreads();
    if (tid == 0) {
        int n = 0;
        for (int j = 0; j < SEQL; j++)
            if (flag[j]) list[n++] = sw[j] * EMBED;  // pre-multiplied offset
        nkeep = n;
    }
    __syncthreads();

    const float* __restrict__ Wt = g_Wt;
    float acc = b_hidden[tid];
    int n = nkeep;
    int j = 0;
    for (; j + 4 <= n; j += 4) {   // 4 outstanding coalesced loads per thread
        float a0 = Wt[list[j + 0] + tid];
        float a1 = Wt[list[j + 1] + tid];
        float a2 = Wt[list[j + 2] + tid];
        float a3 = Wt[list[j + 3] + tid];
        acc += a0 + a1 + a2 + a3;
    }
    for (; j < n; j++) acc += Wt[list[j] + tid];

    hidden[(size_t)b * EMBED + tid] = tanhf(acc);
}

// ---------------------------------------------------------------------------
// pi head: logits = hidden @ W_pi^T + b_pi, softmax over COMP, output
// transposed: out[c * BATCH + b].  8 batch rows per block, 320 threads
// (thread = component, tid<300 active in GEMM).
// ---------------------------------------------------------------------------
#define RB 8
__global__ __launch_bounds__(320) void pi_kernel(
    const float* __restrict__ hidden,
    const float* __restrict__ b_pi,
    float* __restrict__ out) {
    __shared__ float sh[RB][EMBED];      // 16 KB
    __shared__ float sl[RB][COMP + 4];   // ~9.7 KB
    __shared__ float rmax[RB], rsum[RB];

    int b0 = blockIdx.x * RB;
    int tid = threadIdx.x;
    const float* __restrict__ Wpit = g_Wpit;

    for (int i = tid; i < RB * EMBED; i += 320)
        sh[i >> 9][i & (EMBED - 1)] = hidden[(size_t)(b0 + (i >> 9)) * EMBED + (i & (EMBED - 1))];
    __syncthreads();

    if (tid < COMP) {
        float acc[RB];
        float bp = b_pi[tid];
#pragma unroll
        for (int r = 0; r < RB; r++) acc[r] = bp;

        for (int k = 0; k < EMBED; k += 4) {
            float4 h4[RB];
#pragma unroll
            for (int r = 0; r < RB; r++)
                h4[r] = *(const float4*)&sh[r][k];
#pragma unroll
            for (int s = 0; s < 4; s++) {
                float w = Wpit[(size_t)(k + s) * COMP + tid];
#pragma unroll
                for (int r = 0; r < RB; r++)
                    acc[r] = fmaf(w, ((const float*)&h4[r])[s], acc[r]);
            }
        }
#pragma unroll
        for (int r = 0; r < RB; r++) sl[r][tid] = acc[r];
    }
    __syncthreads();

    int wid = tid >> 5, lane = tid & 31;
    if (wid < RB) {
        float m = -INFINITY;
        for (int c = lane; c < COMP; c += 32) m = fmaxf(m, sl[wid][c]);
#pragma unroll
        for (int o = 16; o; o >>= 1) m = fmaxf(m, __shfl_xor_sync(0xFFFFFFFFu, m, o));
        float s = 0.f;
        for (int c = lane; c < COMP; c += 32) s += __expf(sl[wid][c] - m);
#pragma unroll
        for (int o = 16; o; o >>= 1) s += __shfl_xor_sync(0xFFFFFFFFu, s, o);
        if (lane == 0) { rmax[wid] = m; rsum[wid] = 1.0f / s; }
    }
    __syncthreads();

    // out[c * BATCH + b0 + r] : r-fastest mapping -> 32B-coalesced runs of 8
    for (int idx = tid; idx < COMP * RB; idx += 320) {
        int c = idx / RB, r = idx - c * RB;
        out[(size_t)c * BATCH + b0 + r] = __expf(sl[r][c] - rmax[r]) * rsum[r];
    }
}

// ---------------------------------------------------------------------------
// sigma_out = exp(sigma), mu passthrough
// ---------------------------------------------------------------------------
__global__ void tail_kernel(const float* __restrict__ mu,
                            const float* __restrict__ sigma,
                            float* __restrict__ out) {
    int i = blockIdx.x * blockDim.x + threadIdx.x;
    if (i < COMP * 2) {
        out[(size_t)COMP * BATCH + i] = expf(sigma[i]);
        out[(size_t)COMP * BATCH + COMP * 2 + i] = mu[i];
    }
}

extern "C" void kernel_launch(void* const* d_in, const int* in_sizes, int n_in,
                              void* d_out, int out_size) {
    // --- Resolve inputs by element count (robust to metadata-order surprises).
    // Expected: words=409600(first), features=4096, mask=409600(second),
    // W_hidden=25600000, b_hidden=512, W_pi=153600, b_pi=300, mu=600, sigma=600.
    int i_words = 0, i_Wh = 3, i_bh = 4, i_Wpi = 5, i_bpi = 6, i_mu = 7, i_sg = 8;
    {
        int seen409600 = 0, seen600 = 0;
        for (int i = 0; i < n_in; i++) {
            int s = in_sizes[i];
            if (s == BATCH * SEQL) { if (seen409600 == 0) i_words = i; seen409600++; }
            else if (s == EMBED * VOCAB) i_Wh = i;
            else if (s == EMBED) i_bh = i;
            else if (s == COMP * EMBED) i_Wpi = i;
            else if (s == COMP) i_bpi = i;
            else if (s == COMP * 2) { if (seen600 == 0) i_mu = i; else i_sg = i; seen600++; }
        }
    }

    const void*  words    = d_in[i_words];
    const float* W_hidden = (const float*)d_in[i_Wh];
    const float* b_hidden = (const float*)d_in[i_bh];
    const float* W_pi     = (const float*)d_in[i_Wpi];
    const float* b_pi     = (const float*)d_in[i_bpi];
    const float* mu       = (const float*)d_in[i_mu];
    const float* sigma    = (const float*)d_in[i_sg];
    float* out = (float*)d_out;

    void* p_Wt = nullptr;   cudaGetSymbolAddress(&p_Wt, g_Wt);
    void* p_Wpit = nullptr; cudaGetSymbolAddress(&p_Wpit, g_Wpit);
    void* p_hid = nullptr;  cudaGetSymbolAddress(&p_hid, g_hidden);
    float* Wt = (float*)p_Wt;
    float* Wpit = (float*)p_Wpit;
    float* hidden = (float*)p_hid;

    // 0) detect words dtype (int32 vs int64)
    detect_dtype_k<<<1, 32>>>((const int*)words);
    // 1) transpose W_hidden [512,50000] -> Wt [50000,512]
    {
        dim3 grid((VOCAB + 31) / 32, (EMBED + 31) / 32);
        transpose_k<<<grid, dim3(32, 8)>>>(W_hidden, Wt, EMBED, VOCAB);
    }
    // 2) transpose W_pi [300,512] -> Wpit [512,300]
    {
        dim3 grid((EMBED + 31) / 32, (COMP + 31) / 32);
        transpose_k<<<grid, dim3(32, 8)>>>(W_pi, Wpit, COMP, EMBED);
    }
    // 3) bag-of-words gather-sum + tanh
    bow_kernel<<<BATCH, EMBED>>>(words, b_hidden, hidden);
    // 4) pi head (GEMM + softmax, transposed store)
    pi_kernel<<<BATCH / RB, 320>>>(hidden, b_pi, out);
    // 5) sigma/mu tail
    tail_kernel<<<3, 256>>>(mu, sigma, out);
}

// round 5
// speedup vs baseline: 1.6709x; 1.6709x over previous
#include <cuda_runtime.h>
#include <cuda_fp16.h>
#include <math.h>

#define VOCAB 50000
#define EMBED 512
#define COMP  300
#define BATCH 2048
#define SEQL  200

// Scratch (no allocations allowed -> __device__ globals)
__device__ __half g_Wt[(size_t)VOCAB * EMBED];     // W_hidden^T in fp16: [VOCAB, EMBED]
__device__ float  g_hidden[(size_t)BATCH * EMBED]; // tanh hidden: [BATCH, EMBED]
__device__ int    g_is64;                          // 1 if words buffer is int64

// ---------------------------------------------------------------------------
// Detect whether the words buffer is int64 (little-endian: odd int32 words all
// zero) or int32. Deterministic for fixed input.
// ---------------------------------------------------------------------------
__global__ void detect_dtype_k(const int* __restrict__ w32) {
    if (threadIdx.x == 0) {
        int all_zero_odd = 1;
        for (int i = 1; i < 128; i += 2)
            if (w32[i] != 0) { all_zero_odd = 0; break; }
        g_is64 = all_zero_odd;
    }
}

// ---------------------------------------------------------------------------
// Transpose + fp32->fp16 convert: in[EMBED, VOCAB] -> out[VOCAB, EMBED] half
// ---------------------------------------------------------------------------
__global__ void transpose_h_k(const float* __restrict__ in, __half* __restrict__ out) {
    __shared__ float tile[32][33];
    int c0 = blockIdx.x * 32, r0 = blockIdx.y * 32;   // c over VOCAB, r over EMBED
    int x = c0 + threadIdx.x;
#pragma unroll
    for (int i = 0; i < 32; i += 8) {
        int y = r0 + threadIdx.y + i;
        if (x < VOCAB && y < EMBED)
            tile[threadIdx.y + i][threadIdx.x] = in[(size_t)y * VOCAB + x];
    }
    __syncthreads();
    x = r0 + threadIdx.x;                             // x over EMBED now
#pragma unroll
    for (int i = 0; i < 32; i += 8) {
        int y = c0 + threadIdx.y + i;                 // y over VOCAB
        if (x < EMBED && y < VOCAB)
            out[(size_t)y * EMBED + x] = __float2half_rn(tile[threadIdx.x][threadIdx.y + i]);
    }
}

// ---------------------------------------------------------------------------
// Bag-of-words gather-sum + tanh. One block per batch row, 256 threads, each
// thread owns a half2 (2 embedding dims). Bitmap dedup (O(1) per word),
// order-free compaction, MLP=8 gather.
// ---------------------------------------------------------------------------
#define BM_WORDS ((VOCAB + 31) / 32)
__global__ __launch_bounds__(256) void bow_kernel(
    const void* __restrict__ words,
    const float* __restrict__ b_hidden,
    float* __restrict__ hidden) {
    __shared__ unsigned bm[BM_WORDS];   // 6252 B vocab bitmap
    __shared__ int list[SEQL];          // unique word row offsets (half2 units)
    __shared__ int nkeep;

    int b = blockIdx.x;
    int tid = threadIdx.x;
    int is64 = g_is64;

    for (int i = tid; i < BM_WORDS; i += 256) bm[i] = 0u;
    if (tid == 0) nkeep = 0;
    __syncthreads();

    if (tid < SEQL) {
        int w;
        if (is64)
            w = (int)((const long long*)words)[(size_t)b * SEQL + tid];
        else
            w = ((const int*)words)[(size_t)b * SEQL + tid];
        if (w < 0) w = 0;
        if (w >= VOCAB) w = VOCAB - 1;
        unsigned m = 1u << (w & 31);
        unsigned old = atomicOr(&bm[w >> 5], m);
        if (!(old & m)) {
            int p = atomicAdd(&nkeep, 1);
            list[p] = w * (EMBED / 2);   // offset in half2 units
        }
    }
    __syncthreads();

    const __half2* __restrict__ Wt2 = (const __half2*)g_Wt;
    float2 acc = *(const float2*)&b_hidden[2 * tid];
    int n = nkeep;
    int j = 0;
    for (; j + 8 <= n; j += 8) {     // 8 outstanding coalesced 4B loads/thread
        __half2 v[8];
#pragma unroll
        for (int u = 0; u < 8; u++) v[u] = __ldg(&Wt2[list[j + u] + tid]);
#pragma unroll
        for (int u = 0; u < 8; u++) {
            float2 f = __half22float2(v[u]);
            acc.x += f.x; acc.y += f.y;
        }
    }
    for (; j < n; j++) {
        float2 f = __half22float2(__ldg(&Wt2[list[j] + tid]));
        acc.x += f.x; acc.y += f.y;
    }

    float2 o; o.x = tanhf(acc.x); o.y = tanhf(acc.y);
    *(float2*)&hidden[(size_t)b * EMBED + 2 * tid] = o;
}

// ---------------------------------------------------------------------------
// pi head: logits = hidden @ W_pi^T + b_pi, softmax over COMP, transposed out.
// 8 batch rows per block as 4 packed pairs; fma.rn.f32x2 doubles fp32 tput.
// Hidden stored pair-interleaved in smem so LDS.128 yields packed operands.
// ---------------------------------------------------------------------------
#define RB 8
#define NP (RB / 2)

__device__ __forceinline__ unsigned long long pk2(float lo, float hi) {
    unsigned long long r;
    asm("mov.b64 %0, {%1, %2};" : "=l"(r) : "f"(lo), "f"(hi));
    return r;
}
#define FMA2(acc, a, b) \
    asm("fma.rn.f32x2 %0, %1, %2, %0;" : "+l"(acc) : "l"(a), "l"(b))

__global__ __launch_bounds__(320) void pi_kernel(
    const float* __restrict__ hidden,
    const float* __restrict__ W_pi,
    const float* __restrict__ b_pi,
    float* __restrict__ out) {
    __shared__ __align__(16) float2 shp[NP][EMBED];  // pair-interleaved: 16 KB
    __shared__ float sl[RB][COMP + 4];               // logits
    __shared__ float rmax[RB], rsum[RB];

    int b0 = blockIdx.x * RB;
    int tid = threadIdx.x;

    // load hidden rows b0..b0+7, interleaving row pairs (2p, 2p+1)
    {
        float* shpf = (float*)shp;
        for (int idx = tid; idx < RB * EMBED; idx += 320) {
            int r = idx >> 9, k = idx & (EMBED - 1);
            shpf[(((r >> 1) * EMBED) + k) * 2 + (r & 1)] =
                hidden[(size_t)(b0 + r) * EMBED + k];
        }
    }
    __syncthreads();

    if (tid < COMP) {
        unsigned long long acc[NP];
        float bp = b_pi[tid];
#pragma unroll
        for (int p = 0; p < NP; p++) acc[p] = pk2(bp, bp);

        const float* __restrict__ wrow = W_pi + (size_t)tid * EMBED;
        for (int k = 0; k < EMBED; k += 4) {
            float4 w4 = *(const float4*)&wrow[k];
            unsigned long long ws0 = pk2(w4.x, w4.x);
            unsigned long long ws1 = pk2(w4.y, w4.y);
            unsigned long long ws2 = pk2(w4.z, w4.z);
            unsigned long long ws3 = pk2(w4.w, w4.w);
#pragma unroll
            for (int p = 0; p < NP; p++) {
                float4 h01 = *(const float4*)&shp[p][k];      // (h2p_k, h2p1_k, h2p_k1, h2p1_k1)
                float4 h23 = *(const float4*)&shp[p][k + 2];
                unsigned long long a0, a1, a2, a3;
                asm("mov.b64 %0, {%1, %2};" : "=l"(a0) : "f"(h01.x), "f"(h01.y));
                asm("mov.b64 %0, {%1, %2};" : "=l"(a1) : "f"(h01.z), "f"(h01.w));
                asm("mov.b64 %0, {%1, %2};" : "=l"(a2) : "f"(h23.x), "f"(h23.y));
                asm("mov.b64 %0, {%1, %2};" : "=l"(a3) : "f"(h23.z), "f"(h23.w));
                FMA2(acc[p], a0, ws0);
                FMA2(acc[p], a1, ws1);
                FMA2(acc[p], a2, ws2);
                FMA2(acc[p], a3, ws3);
            }
        }
#pragma unroll
        for (int p = 0; p < NP; p++) {
            float lo, hi;
            asm("mov.b64 {%0, %1}, %2;" : "=f"(lo), "=f"(hi) : "l"(acc[p]));
            sl[2 * p][tid] = lo;
            sl[2 * p + 1][tid] = hi;
        }
    }
    __syncthreads();

    int wid = tid >> 5, lane = tid & 31;
    if (wid < RB) {
        float m = -INFINITY;
        for (int c = lane; c < COMP; c += 32) m = fmaxf(m, sl[wid][c]);
#pragma unroll
        for (int o = 16; o; o >>= 1) m = fmaxf(m, __shfl_xor_sync(0xFFFFFFFFu, m, o));
        float s = 0.f;
        for (int c = lane; c < COMP; c += 32) s += __expf(sl[wid][c] - m);
#pragma unroll
        for (int o = 16; o; o >>= 1) s += __shfl_xor_sync(0xFFFFFFFFu, s, o);
        if (lane == 0) { rmax[wid] = m; rsum[wid] = 1.0f / s; }
    }
    __syncthreads();

    // out[c * BATCH + b0 + r] : r-fastest mapping -> 32B-coalesced runs of 8
    for (int idx = tid; idx < COMP * RB; idx += 320) {
        int c = idx / RB, r = idx - c * RB;
        out[(size_t)c * BATCH + b0 + r] = __expf(sl[r][c] - rmax[r]) * rsum[r];
    }
}

// ---------------------------------------------------------------------------
// sigma_out = exp(sigma), mu passthrough
// ---------------------------------------------------------------------------
__global__ void tail_kernel(const float* __restrict__ mu,
                            const float* __restrict__ sigma,
                            float* __restrict__ out) {
    int i = blockIdx.x * blockDim.x + threadIdx.x;
    if (i < COMP * 2) {
        out[(size_t)COMP * BATCH + i] = expf(sigma[i]);
        out[(size_t)COMP * BATCH + COMP * 2 + i] = mu[i];
    }
}

extern "C" void kernel_launch(void* const* d_in, const int* in_sizes, int n_in,
                              void* d_out, int out_size) {
    // Resolve inputs by element count (robust to metadata-order surprises).
    int i_words = 0, i_Wh = 3, i_bh = 4, i_Wpi = 5, i_bpi = 6, i_mu = 7, i_sg = 8;
    {
        int seen409600 = 0, seen600 = 0;
        for (int i = 0; i < n_in; i++) {
            int s = in_sizes[i];
            if (s == BATCH * SEQL) { if (seen409600 == 0) i_words = i; seen409600++; }
            else if (s == EMBED * VOCAB) i_Wh = i;
            else if (s == EMBED) i_bh = i;
            else if (s == COMP * EMBED) i_Wpi = i;
            else if (s == COMP) i_bpi = i;
            else if (s == COMP * 2) { if (seen600 == 0) i_mu = i; else i_sg = i; seen600++; }
        }
    }

    const void*  words    = d_in[i_words];
    const float* W_hidden = (const float*)d_in[i_Wh];
    const float* b_hidden = (const float*)d_in[i_bh];
    const float* W_pi     = (const float*)d_in[i_Wpi];
    const float* b_pi     = (const float*)d_in[i_bpi];
    const float* mu       = (const float*)d_in[i_mu];
    const float* sigma    = (const float*)d_in[i_sg];
    float* out = (float*)d_out;

    void* p_Wt = nullptr;  cudaGetSymbolAddress(&p_Wt, g_Wt);
    void* p_hid = nullptr; cudaGetSymbolAddress(&p_hid, g_hidden);
    __half* Wt = (__half*)p_Wt;
    float* hidden = (float*)p_hid;

    // 0) detect words dtype (int32 vs int64)
    detect_dtype_k<<<1, 32>>>((const int*)words);
    // 1) transpose+convert W_hidden [512,50000] f32 -> Wt [50000,512] f16
    {
        dim3 grid((VOCAB + 31) / 32, (EMBED + 31) / 32);
        transpose_h_k<<<grid, dim3(32, 8)>>>(W_hidden, Wt);
    }
    // 2) bag-of-words gather-sum + tanh
    bow_kernel<<<BATCH, 256>>>(words, b_hidden, hidden);
    // 3) pi head (packed-f32x2 GEMM + softmax, transposed store)
    pi_kernel<<<BATCH / RB, 320>>>(hidden, W_pi, b_pi, out);
    // 4) sigma/mu tail
    tail_kernel<<<3, 256>>>(mu, sigma, out);
}